// round 2
// baseline (speedup 1.0000x reference)
#include <cuda_runtime.h>
#include <cuda_bf16.h>

// Problem constants: B=8, H=12, N=1024, D=64, fp32.
#define BHCOUNT 96
#define NSEQ    1024
#define DHEAD   64
#define BM      128     // query rows per CTA
#define BN      64      // kv rows per tile
#define NTHREADS 256
#define SCALE   0.125f  // 1/sqrt(64)

// smem strides (floats). Qt/Pt: [D or BN][BM+4] transposed; Kt: [D][BN+4]; Vs: [BN][D].
#define QT_STRIDE 132
#define KT_STRIDE 68
#define PT_STRIDE 132

#define QT_FLOATS (64 * QT_STRIDE)           // 8448
#define KT_FLOATS (64 * KT_STRIDE)           // 4352
#define VS_FLOATS (64 * 64)                  // 4096
#define PT_FLOATS (64 * PT_STRIDE)           // 8448
#define SMEM_FLOATS (QT_FLOATS + KT_FLOATS + VS_FLOATS + PT_FLOATS)
#define SMEM_BYTES (SMEM_FLOATS * 4)         // 101376 B

__global__ __launch_bounds__(NTHREADS, 2)
void attn_fwd_fp32(const float* __restrict__ Qg_,
                   const float* __restrict__ Kg_,
                   const float* __restrict__ Vg_,
                   float* __restrict__ Og_)
{
    extern __shared__ float smem[];
    float* Qt = smem;                         // Qt[d][r], pre-scaled by 1/sqrt(d)
    float* Kt = Qt + QT_FLOATS;               // Kt[d][c]
    float* Vs = Kt + KT_FLOATS;               // Vs[k][c] row-major
    float* Pt = Vs + VS_FLOATS;               // Pt[k][r]

    const int tid = threadIdx.x;
    const int tx  = tid & 7;                  // 8 column groups (8 cols each)
    const int ty  = tid >> 3;                 // 32 row groups (4 rows each)
    const int q0  = blockIdx.x * BM;          // 0..896
    const int bh  = blockIdx.y;               // 0..95

    const float* Qg = Qg_ + ((size_t)bh * NSEQ + q0) * DHEAD;
    const float* Kg = Kg_ + (size_t)bh * NSEQ * DHEAD;
    const float* Vg = Vg_ + (size_t)bh * NSEQ * DHEAD;
    float*       Og = Og_ + ((size_t)bh * NSEQ + q0) * DHEAD;

    // ---- Load Q tile (128x64) transposed into Qt, folding in the softmax scale ----
    #pragma unroll
    for (int it = 0; it < 8; ++it) {
        int idx = (it * NTHREADS + tid) * 4;      // 0..8191
        int r = idx >> 6;
        int d = idx & 63;
        float4 v = *(const float4*)(Qg + r * DHEAD + d);
        Qt[(d + 0) * QT_STRIDE + r] = v.x * SCALE;
        Qt[(d + 1) * QT_STRIDE + r] = v.y * SCALE;
        Qt[(d + 2) * QT_STRIDE + r] = v.z * SCALE;
        Qt[(d + 3) * QT_STRIDE + r] = v.w * SCALE;
    }

    float m[4], l[4];
    float acc[4][8];
    #pragma unroll
    for (int i = 0; i < 4; ++i) {
        m[i] = -1e30f;
        l[i] = 0.0f;
        #pragma unroll
        for (int j = 0; j < 8; ++j) acc[i][j] = 0.0f;
    }

    const int r0 = ty * 4;
    const int c0 = tx * 8;

    for (int t = 0; t < NSEQ / BN; ++t) {
        __syncthreads();   // previous iteration fully done (Kt/Vs/Pt reads complete)

        // ---- Load K tile (64x64) transposed + V tile (64x64) row-major ----
        #pragma unroll
        for (int it = 0; it < 4; ++it) {
            int idx = (it * NTHREADS + tid) * 4;  // 0..4095
            int c = idx >> 6;
            int d = idx & 63;
            float4 kv = *(const float4*)(Kg + ((size_t)(t * BN + c)) * DHEAD + d);
            Kt[(d + 0) * KT_STRIDE + c] = kv.x;
            Kt[(d + 1) * KT_STRIDE + c] = kv.y;
            Kt[(d + 2) * KT_STRIDE + c] = kv.z;
            Kt[(d + 3) * KT_STRIDE + c] = kv.w;
            float4 vv = *(const float4*)(Vg + (size_t)t * BN * DHEAD + idx);
            *(float4*)(Vs + idx) = vv;
        }
        __syncthreads();

        // ---- S = (Q*scale) @ K^T : per-thread 4x8 tile ----
        float s[4][8];
        #pragma unroll
        for (int i = 0; i < 4; ++i)
            #pragma unroll
            for (int j = 0; j < 8; ++j) s[i][j] = 0.0f;

        #pragma unroll 8
        for (int d = 0; d < 64; ++d) {
            float4 a  = *(const float4*)(Qt + d * QT_STRIDE + r0);
            float4 b0 = *(const float4*)(Kt + d * KT_STRIDE + c0);
            float4 b1 = *(const float4*)(Kt + d * KT_STRIDE + c0 + 4);
            float av[4] = {a.x, a.y, a.z, a.w};
            float bv[8] = {b0.x, b0.y, b0.z, b0.w, b1.x, b1.y, b1.z, b1.w};
            #pragma unroll
            for (int i = 0; i < 4; ++i)
                #pragma unroll
                for (int j = 0; j < 8; ++j)
                    s[i][j] = fmaf(av[i], bv[j], s[i][j]);
        }

        // ---- Online softmax (row stats across the 8 lanes of each row group) ----
        #pragma unroll
        for (int i = 0; i < 4; ++i) {
            float mt = s[i][0];
            #pragma unroll
            for (int j = 1; j < 8; ++j) mt = fmaxf(mt, s[i][j]);
            mt = fmaxf(mt, __shfl_xor_sync(0xffffffffu, mt, 1, 8));
            mt = fmaxf(mt, __shfl_xor_sync(0xffffffffu, mt, 2, 8));
            mt = fmaxf(mt, __shfl_xor_sync(0xffffffffu, mt, 4, 8));

            float mn = fmaxf(m[i], mt);
            float alpha = __expf(m[i] - mn);
            m[i] = mn;

            float rs = 0.0f;
            #pragma unroll
            for (int j = 0; j < 8; ++j) {
                float p = __expf(s[i][j] - mn);
                s[i][j] = p;
                rs += p;
            }
            rs += __shfl_xor_sync(0xffffffffu, rs, 1, 8);
            rs += __shfl_xor_sync(0xffffffffu, rs, 2, 8);
            rs += __shfl_xor_sync(0xffffffffu, rs, 4, 8);

            l[i] = l[i] * alpha + rs;
            #pragma unroll
            for (int j = 0; j < 8; ++j) acc[i][j] *= alpha;
        }

        // ---- Write P transposed: Pt[c][r0..r0+3] as float4 (rows contiguous) ----
        #pragma unroll
        for (int j = 0; j < 8; ++j) {
            float4 pv = make_float4(s[0][j], s[1][j], s[2][j], s[3][j]);
            *(float4*)(Pt + (c0 + j) * PT_STRIDE + r0) = pv;
        }
        __syncthreads();

        // ---- O += P @ V : per-thread 4x8 ----
        #pragma unroll 8
        for (int k = 0; k < 64; ++k) {
            float4 a  = *(const float4*)(Pt + k * PT_STRIDE + r0);
            float4 v0 = *(const float4*)(Vs + k * 64 + c0);
            float4 v1 = *(const float4*)(Vs + k * 64 + c0 + 4);
            float av[4] = {a.x, a.y, a.z, a.w};
            float vv[8] = {v0.x, v0.y, v0.z, v0.w, v1.x, v1.y, v1.z, v1.w};
            #pragma unroll
            for (int i = 0; i < 4; ++i)
                #pragma unroll
                for (int j = 0; j < 8; ++j)
                    acc[i][j] = fmaf(av[i], vv[j], acc[i][j]);
        }
    }

    // ---- Normalize and write out ----
    #pragma unroll
    for (int i = 0; i < 4; ++i) {
        int r = r0 + i;
        float inv = 1.0f / l[i];
        float4 o0 = make_float4(acc[i][0] * inv, acc[i][1] * inv,
                                acc[i][2] * inv, acc[i][3] * inv);
        float4 o1 = make_float4(acc[i][4] * inv, acc[i][5] * inv,
                                acc[i][6] * inv, acc[i][7] * inv);
        *(float4*)(Og + (size_t)r * DHEAD + c0)     = o0;
        *(float4*)(Og + (size_t)r * DHEAD + c0 + 4) = o1;
    }
}

extern "C" void kernel_launch(void* const* d_in, const int* in_sizes, int n_in,
                              void* d_out, int out_size)
{
    const float* Q = (const float*)d_in[0];
    const float* K = (const float*)d_in[1];
    const float* V = (const float*)d_in[2];
    float* O = (float*)d_out;

    // Idempotent, host-side, not a stream op — safe under graph capture.
    cudaFuncSetAttribute(attn_fwd_fp32,
                         cudaFuncAttributeMaxDynamicSharedMemorySize, SMEM_BYTES);

    dim3 grid(NSEQ / BM, BHCOUNT);   // 8 x 96 = 768 CTAs
    dim3 block(NTHREADS);
    attn_fwd_fp32<<<grid, block, SMEM_BYTES>>>(Q, K, V, O);
}

// round 5
// speedup vs baseline: 3.6720x; 3.6720x over previous
#include <cuda_runtime.h>
#include <cstdint>

// B=8, H=12, N=1024, D=64, fp32 in/out.  Baseline PTX (compute_100): mma.sync tf32.
#define BHCOUNT  96
#define NSEQ     1024
#define DHEAD    64
#define BM       128
#define BN       64
#define NTILES   (NSEQ / BN)
#define NTHREADS 256
#define SCALE    0.125f

// smem word offsets.  K stride 68 (bank = 4g+t), V stride 72 (bank = 8t+g), P stride 68.
#define KSTR 68
#define VSTR 72
#define PSTR 68
#define K0_OFF 0
#define K1_OFF (64 * KSTR)                 // 4352
#define V0_OFF (2 * 64 * KSTR)             // 8704
#define V1_OFF (V0_OFF + 64 * VSTR)        // 13312
#define P_OFF  (V0_OFF + 2 * 64 * VSTR)    // 17920
#define SMEM_WORDS (P_OFF + 8 * 16 * PSTR) // 26624
#define SMEM_BYTES (SMEM_WORDS * 4)        // 106496

__device__ __forceinline__ uint32_t f2tf(float x) {
    uint32_t r; asm("cvt.rna.tf32.f32 %0, %1;" : "=r"(r) : "f"(x)); return r;
}

__device__ __forceinline__ void mma8(float* d, const uint32_t* a, uint32_t b0, uint32_t b1) {
    asm volatile(
        "mma.sync.aligned.m16n8k8.row.col.f32.tf32.tf32.f32 "
        "{%0,%1,%2,%3}, {%4,%5,%6,%7}, {%8,%9}, {%0,%1,%2,%3};"
        : "+f"(d[0]), "+f"(d[1]), "+f"(d[2]), "+f"(d[3])
        : "r"(a[0]), "r"(a[1]), "r"(a[2]), "r"(a[3]), "r"(b0), "r"(b1));
}

__global__ __launch_bounds__(NTHREADS)
void attn_mma_tf32(const float* __restrict__ Qg_,
                   const float* __restrict__ Kg_,
                   const float* __restrict__ Vg_,
                   float* __restrict__ Og_)
{
    extern __shared__ float sm[];
    const int tid  = threadIdx.x;
    const int wid  = tid >> 5;
    const int lane = tid & 31;
    const int g    = lane >> 2;     // 0..7 (row group)
    const int lt   = lane & 3;      // 0..3 (thread-in-group)

    const int q0 = blockIdx.x * BM;
    const int bh = blockIdx.y;
    const float* Qb = Qg_ + ((size_t)bh * NSEQ + q0 + wid * 16) * DHEAD;
    const float* Kb = Kg_ + (size_t)bh * NSEQ * DHEAD;
    const float* Vb = Vg_ + (size_t)bh * NSEQ * DHEAD;
    float*       Ob = Og_ + ((size_t)bh * NSEQ + q0 + wid * 16) * DHEAD;

    // ---- Q fragments (held in regs for all tiles), softmax scale folded in ----
    uint32_t qa[8][4];
    #pragma unroll
    for (int kk = 0; kk < 8; ++kk) {
        qa[kk][0] = f2tf(Qb[(g)     * 64 + 8 * kk + lt]     * SCALE);
        qa[kk][1] = f2tf(Qb[(g + 8) * 64 + 8 * kk + lt]     * SCALE);
        qa[kk][2] = f2tf(Qb[(g)     * 64 + 8 * kk + lt + 4] * SCALE);
        qa[kk][3] = f2tf(Qb[(g + 8) * 64 + 8 * kk + lt + 4] * SCALE);
    }

    float o[8][4];
    #pragma unroll
    for (int nb = 0; nb < 8; ++nb)
        { o[nb][0] = 0.f; o[nb][1] = 0.f; o[nb][2] = 0.f; o[nb][3] = 0.f; }
    float m0 = -1e30f, m1 = -1e30f, l0 = 0.f, l1 = 0.f;

    float4 kst[4], vst[4];

    // ---- prologue: stage tile 0 ----
    {
        const float4* kp = (const float4*)Kb;
        const float4* vp = (const float4*)Vb;
        #pragma unroll
        for (int i = 0; i < 4; ++i) { int u = i * NTHREADS + tid; kst[i] = kp[u]; vst[i] = vp[u]; }
        float* kd = sm + K0_OFF; float* vd = sm + V0_OFF;
        #pragma unroll
        for (int i = 0; i < 4; ++i) {
            int u = i * NTHREADS + tid;
            int row = u >> 4, c4 = (u & 15) * 4;
            uint4 kq = { f2tf(kst[i].x), f2tf(kst[i].y), f2tf(kst[i].z), f2tf(kst[i].w) };
            uint4 vq = { f2tf(vst[i].x), f2tf(vst[i].y), f2tf(vst[i].z), f2tf(vst[i].w) };
            *(uint4*)(kd + row * KSTR + c4) = kq;
            *(uint4*)(vd + row * VSTR + c4) = vq;
        }
    }
    __syncthreads();

    uint32_t* pw = (uint32_t*)(sm + P_OFF + wid * 16 * PSTR);

    #pragma unroll 1
    for (int t = 0; t < NTILES; ++t) {
        const int cur = t & 1;
        const uint32_t* kbu = (const uint32_t*)(sm + (cur ? K1_OFF : K0_OFF));
        const uint32_t* vbu = (const uint32_t*)(sm + (cur ? V1_OFF : V0_OFF));
        float* kn = sm + (cur ? K0_OFF : K1_OFF);
        float* vn = sm + (cur ? V0_OFF : V1_OFF);

        // (1) issue gmem loads for next tile (latency hidden under S-GEMM/softmax)
        if (t + 1 < NTILES) {
            const float4* kp = (const float4*)(Kb + (size_t)(t + 1) * BN * DHEAD);
            const float4* vp = (const float4*)(Vb + (size_t)(t + 1) * BN * DHEAD);
            #pragma unroll
            for (int i = 0; i < 4; ++i) { int u = i * NTHREADS + tid; kst[i] = kp[u]; vst[i] = vp[u]; }
        }

        // (2) S = Q @ K^T  (per warp: 16 x 64, k=64)
        float s[8][4];
        #pragma unroll
        for (int nb = 0; nb < 8; ++nb)
            { s[nb][0] = 0.f; s[nb][1] = 0.f; s[nb][2] = 0.f; s[nb][3] = 0.f; }
        #pragma unroll
        for (int nb = 0; nb < 8; ++nb) {
            const uint32_t* kr = kbu + (8 * nb + g) * KSTR;
            #pragma unroll
            for (int kk = 0; kk < 8; ++kk) {
                uint32_t b0 = kr[8 * kk + lt];
                uint32_t b1 = kr[8 * kk + lt + 4];
                mma8(s[nb], qa[kk], b0, b1);
            }
        }

        // (3) online softmax: rows g (s[.][0..1]) and g+8 (s[.][2..3])
        float mx0 = m0, mx1 = m1;
        #pragma unroll
        for (int nb = 0; nb < 8; ++nb) {
            mx0 = fmaxf(mx0, fmaxf(s[nb][0], s[nb][1]));
            mx1 = fmaxf(mx1, fmaxf(s[nb][2], s[nb][3]));
        }
        mx0 = fmaxf(mx0, __shfl_xor_sync(0xffffffffu, mx0, 1));
        mx0 = fmaxf(mx0, __shfl_xor_sync(0xffffffffu, mx0, 2));
        mx1 = fmaxf(mx1, __shfl_xor_sync(0xffffffffu, mx1, 1));
        mx1 = fmaxf(mx1, __shfl_xor_sync(0xffffffffu, mx1, 2));

        const float a0 = __expf(m0 - mx0);
        const float a1 = __expf(m1 - mx1);
        float rs0 = 0.f, rs1 = 0.f;
        #pragma unroll
        for (int nb = 0; nb < 8; ++nb) {
            s[nb][0] = __expf(s[nb][0] - mx0);
            s[nb][1] = __expf(s[nb][1] - mx0);
            s[nb][2] = __expf(s[nb][2] - mx1);
            s[nb][3] = __expf(s[nb][3] - mx1);
            rs0 += s[nb][0] + s[nb][1];
            rs1 += s[nb][2] + s[nb][3];
        }
        rs0 += __shfl_xor_sync(0xffffffffu, rs0, 1);
        rs0 += __shfl_xor_sync(0xffffffffu, rs0, 2);
        rs1 += __shfl_xor_sync(0xffffffffu, rs1, 1);
        rs1 += __shfl_xor_sync(0xffffffffu, rs1, 2);
        m0 = mx0; m1 = mx1;
        l0 = l0 * a0 + rs0;
        l1 = l1 * a1 + rs1;

        // (4) P round-trip through per-warp smem: C-layout stores -> A-layout loads
        __syncwarp();
        #pragma unroll
        for (int nb = 0; nb < 8; ++nb) {
            uint2 p01 = { f2tf(s[nb][0]), f2tf(s[nb][1]) };
            uint2 p23 = { f2tf(s[nb][2]), f2tf(s[nb][3]) };
            *(uint2*)(pw + (g)     * PSTR + 8 * nb + 2 * lt) = p01;
            *(uint2*)(pw + (g + 8) * PSTR + 8 * nb + 2 * lt) = p23;
        }
        __syncwarp();
        uint32_t pa[8][4];
        #pragma unroll
        for (int kk = 0; kk < 8; ++kk) {
            pa[kk][0] = pw[(g)     * PSTR + 8 * kk + lt];
            pa[kk][1] = pw[(g + 8) * PSTR + 8 * kk + lt];
            pa[kk][2] = pw[(g)     * PSTR + 8 * kk + lt + 4];
            pa[kk][3] = pw[(g + 8) * PSTR + 8 * kk + lt + 4];
        }

        // (5) store staged next tile into the other buffers (LDG long since landed)
        if (t + 1 < NTILES) {
            #pragma unroll
            for (int i = 0; i < 4; ++i) {
                int u = i * NTHREADS + tid;
                int row = u >> 4, c4 = (u & 15) * 4;
                uint4 kq = { f2tf(kst[i].x), f2tf(kst[i].y), f2tf(kst[i].z), f2tf(kst[i].w) };
                uint4 vq = { f2tf(vst[i].x), f2tf(vst[i].y), f2tf(vst[i].z), f2tf(vst[i].w) };
                *(uint4*)(kn + row * KSTR + c4) = kq;
                *(uint4*)(vn + row * VSTR + c4) = vq;
            }
        }

        // (6) O = O*alpha + P @ V
        #pragma unroll
        for (int nb = 0; nb < 8; ++nb) {
            o[nb][0] *= a0; o[nb][1] *= a0; o[nb][2] *= a1; o[nb][3] *= a1;
        }
        #pragma unroll
        for (int nb = 0; nb < 8; ++nb) {
            #pragma unroll
            for (int kk = 0; kk < 8; ++kk) {
                uint32_t b0 = vbu[(8 * kk + lt)     * VSTR + 8 * nb + g];
                uint32_t b1 = vbu[(8 * kk + lt + 4) * VSTR + 8 * nb + g];
                mma8(o[nb], pa[kk], b0, b1);
            }
        }
        __syncthreads();   // buffers consumed; next-iter reads of kn/vn now safe
    }

    // ---- epilogue ----
    const float inv0 = 1.0f / l0;
    const float inv1 = 1.0f / l1;
    #pragma unroll
    for (int nb = 0; nb < 8; ++nb) {
        float2 r0 = { o[nb][0] * inv0, o[nb][1] * inv0 };
        float2 r1 = { o[nb][2] * inv1, o[nb][3] * inv1 };
        *(float2*)(Ob + (g)     * 64 + 8 * nb + 2 * lt) = r0;
        *(float2*)(Ob + (g + 8) * 64 + 8 * nb + 2 * lt) = r1;
    }
}

extern "C" void kernel_launch(void* const* d_in, const int* in_sizes, int n_in,
                              void* d_out, int out_size)
{
    const float* Q = (const float*)d_in[0];
    const float* K = (const float*)d_in[1];
    const float* V = (const float*)d_in[2];
    float* O = (float*)d_out;

    cudaFuncSetAttribute(attn_mma_tf32,
                         cudaFuncAttributeMaxDynamicSharedMemorySize, SMEM_BYTES);

    dim3 grid(NSEQ / BM, BHCOUNT);   // 8 x 96 = 768 CTAs
    attn_mma_tf32<<<grid, NTHREADS, SMEM_BYTES>>>(Q, K, V, O);
}

// round 6
// speedup vs baseline: 7.9979x; 2.1781x over previous
#include <cuda_runtime.h>
#include <cuda_fp16.h>
#include <cstdint>

// B=8, H=12, N=1024, D=64, fp32 in/out.  mma.sync m16n8k16 f16 (f32 accum) + ldmatrix.
#define BHCOUNT  96
#define NSEQ     1024
#define DHEAD    64
#define BM       64            // q rows per CTA (4 warps x m16)
#define BN       64            // kv rows per tile
#define NTILES   (NSEQ / BN)
#define NTHREADS 128
#define SCALE    0.125f

// smem (words): K[64 rows x 36], V[64 x 36], P[4 warps x 16 x 36]; stride 36 w = 144 B = 72 halves
#define RSTR   36
#define KS_W   0
#define VS_W   2304
#define PS_W   4608
#define SMEM_WORDS 6912        // 27648 B (static)

__device__ __forceinline__ uint32_t smem_u32(const void* p) {
    uint32_t a;
    asm("{ .reg .u64 t; cvta.to.shared.u64 t, %1; cvt.u32.u64 %0, t; }" : "=r"(a) : "l"(p));
    return a;
}
__device__ __forceinline__ uint32_t pkh2(float x, float y) {
    __half2 h = __floats2half2_rn(x, y);
    return *(uint32_t*)&h;
}

#define LDSM_X4(d, a) \
    asm volatile("ldmatrix.sync.aligned.m8n8.x4.shared.b16 {%0,%1,%2,%3}, [%4];" \
        : "=r"((d)[0]), "=r"((d)[1]), "=r"((d)[2]), "=r"((d)[3]) : "r"(a))
#define LDSM_X4_T(d, a) \
    asm volatile("ldmatrix.sync.aligned.m8n8.x4.trans.shared.b16 {%0,%1,%2,%3}, [%4];" \
        : "=r"((d)[0]), "=r"((d)[1]), "=r"((d)[2]), "=r"((d)[3]) : "r"(a))

__device__ __forceinline__ void mma16(float* d, const uint32_t* a, uint32_t b0, uint32_t b1) {
    asm volatile(
        "mma.sync.aligned.m16n8k16.row.col.f32.f16.f16.f32 "
        "{%0,%1,%2,%3}, {%4,%5,%6,%7}, {%8,%9}, {%0,%1,%2,%3};"
        : "+f"(d[0]), "+f"(d[1]), "+f"(d[2]), "+f"(d[3])
        : "r"(a[0]), "r"(a[1]), "r"(a[2]), "r"(a[3]), "r"(b0), "r"(b1));
}

__global__ __launch_bounds__(NTHREADS, 4)
void attn_mma_f16(const float* __restrict__ Qg_,
                  const float* __restrict__ Kg_,
                  const float* __restrict__ Vg_,
                  float* __restrict__ Og_)
{
    __shared__ uint32_t sm[SMEM_WORDS];
    const uint32_t smb = smem_u32(sm);
    const int tid  = threadIdx.x;
    const int wid  = tid >> 5;
    const int lane = tid & 31;
    const int g    = lane >> 2;        // 0..7
    const int lt   = lane & 3;         // 0..3

    const int q0 = blockIdx.x * BM;
    const int bh = blockIdx.y;
    const float* Qb = Qg_ + ((size_t)bh * NSEQ + q0 + wid * 16) * DHEAD;
    const float* Kb = Kg_ + (size_t)bh * NSEQ * DHEAD;
    const float* Vb = Vg_ + (size_t)bh * NSEQ * DHEAD;
    float*       Ob = Og_ + ((size_t)bh * NSEQ + q0 + wid * 16) * DHEAD;

    // ---- Q fragments (half2, scale folded), resident all tiles: 16 regs ----
    uint32_t qa[4][4];
    {
        const float* q0r = Qb + g * DHEAD;
        const float* q1r = Qb + (g + 8) * DHEAD;
        #pragma unroll
        for (int kk = 0; kk < 4; ++kk) {
            int c = 16 * kk + 2 * lt;
            float2 x0 = *(const float2*)(q0r + c);
            float2 x1 = *(const float2*)(q1r + c);
            float2 x2 = *(const float2*)(q0r + c + 8);
            float2 x3 = *(const float2*)(q1r + c + 8);
            qa[kk][0] = pkh2(x0.x * SCALE, x0.y * SCALE);
            qa[kk][1] = pkh2(x1.x * SCALE, x1.y * SCALE);
            qa[kk][2] = pkh2(x2.x * SCALE, x2.y * SCALE);
            qa[kk][3] = pkh2(x3.x * SCALE, x3.y * SCALE);
        }
    }

    // ---- per-lane ldmatrix base addresses (byte offsets precomputed) ----
    // K (non-trans): rows 8*(l>>4)+(l&7), col-half chunk +((l>>3)&1)*8; +nbp*2304 +kk*32 at use
    const uint32_t kbase = smb + KS_W * 4
        + (uint32_t)((8 * (lane >> 4) + (lane & 7)) * 144 + ((lane >> 3) & 1) * 16);
    // V (trans): rows (l&15) [+16*kk], cols nbp*16 + (l>>4)*8 halves
    const uint32_t vbase = smb + VS_W * 4
        + (uint32_t)((lane & 15) * 144 + (lane >> 4) * 16);
    // P (non-trans, per warp): rows (l&15), +kk*32
    const uint32_t pbase = smb + (PS_W + wid * 16 * RSTR) * 4
        + (uint32_t)((lane & 15) * 144 + (lane >> 4) * 16);
    uint32_t* pw = sm + PS_W + wid * 16 * RSTR;

    float o[8][4];
    #pragma unroll
    for (int nb = 0; nb < 8; ++nb)
        { o[nb][0] = 0.f; o[nb][1] = 0.f; o[nb][2] = 0.f; o[nb][3] = 0.f; }
    float m0 = -1e30f, m1 = -1e30f, l0 = 0.f, l1 = 0.f;

    for (int t = 0; t < NTILES; ++t) {
        __syncthreads();   // prior tile's ldmatrix reads complete before overwrite

        // ---- stage K,V tile t: LDG.128 -> cvt f16 -> STS.64 (row-major, stride 72h) ----
        {
            const float4* kp = (const float4*)(Kb + (size_t)t * BN * DHEAD);
            const float4* vp = (const float4*)(Vb + (size_t)t * BN * DHEAD);
            #pragma unroll
            for (int i = 0; i < 8; ++i) {
                int idx = i * NTHREADS + tid;          // 0..1023
                int r = idx >> 4, w2 = (idx & 15) * 2; // word offset within row
                float4 kf = kp[idx];
                float4 vf = vp[idx];
                uint2 kh = { pkh2(kf.x, kf.y), pkh2(kf.z, kf.w) };
                uint2 vh = { pkh2(vf.x, vf.y), pkh2(vf.z, vf.w) };
                *(uint2*)(sm + KS_W + r * RSTR + w2) = kh;
                *(uint2*)(sm + VS_W + r * RSTR + w2) = vh;
            }
        }
        __syncthreads();

        // ---- S = Q @ K^T  (per warp 16x64) ----
        float s[8][4];
        #pragma unroll
        for (int nb = 0; nb < 8; ++nb)
            { s[nb][0] = 0.f; s[nb][1] = 0.f; s[nb][2] = 0.f; s[nb][3] = 0.f; }
        #pragma unroll
        for (int nbp = 0; nbp < 4; ++nbp) {
            #pragma unroll
            for (int kk = 0; kk < 4; ++kk) {
                uint32_t b[4];
                LDSM_X4(b, kbase + nbp * 2304 + kk * 32);
                mma16(s[2 * nbp],     qa[kk], b[0], b[1]);
                mma16(s[2 * nbp + 1], qa[kk], b[2], b[3]);
            }
        }

        // ---- online softmax (rows g and g+8) ----
        float mx0 = m0, mx1 = m1;
        #pragma unroll
        for (int nb = 0; nb < 8; ++nb) {
            mx0 = fmaxf(mx0, fmaxf(s[nb][0], s[nb][1]));
            mx1 = fmaxf(mx1, fmaxf(s[nb][2], s[nb][3]));
        }
        mx0 = fmaxf(mx0, __shfl_xor_sync(0xffffffffu, mx0, 1));
        mx0 = fmaxf(mx0, __shfl_xor_sync(0xffffffffu, mx0, 2));
        mx1 = fmaxf(mx1, __shfl_xor_sync(0xffffffffu, mx1, 1));
        mx1 = fmaxf(mx1, __shfl_xor_sync(0xffffffffu, mx1, 2));

        const float a0 = __expf(m0 - mx0);
        const float a1 = __expf(m1 - mx1);
        float rs0 = 0.f, rs1 = 0.f;
        #pragma unroll
        for (int nb = 0; nb < 8; ++nb) {
            s[nb][0] = __expf(s[nb][0] - mx0);
            s[nb][1] = __expf(s[nb][1] - mx0);
            s[nb][2] = __expf(s[nb][2] - mx1);
            s[nb][3] = __expf(s[nb][3] - mx1);
            rs0 += s[nb][0] + s[nb][1];
            rs1 += s[nb][2] + s[nb][3];
        }
        rs0 += __shfl_xor_sync(0xffffffffu, rs0, 1);
        rs0 += __shfl_xor_sync(0xffffffffu, rs0, 2);
        rs1 += __shfl_xor_sync(0xffffffffu, rs1, 1);
        rs1 += __shfl_xor_sync(0xffffffffu, rs1, 2);
        m0 = mx0; m1 = mx1;
        l0 = l0 * a0 + rs0;
        l1 = l1 * a1 + rs1;

        // ---- P -> per-warp smem (half2), then A-fragments via ldmatrix ----
        __syncwarp();
        #pragma unroll
        for (int nb = 0; nb < 8; ++nb) {
            pw[(g)     * RSTR + 4 * nb + lt] = pkh2(s[nb][0], s[nb][1]);
            pw[(g + 8) * RSTR + 4 * nb + lt] = pkh2(s[nb][2], s[nb][3]);
        }
        __syncwarp();
        uint32_t pa[4][4];
        #pragma unroll
        for (int kk = 0; kk < 4; ++kk)
            LDSM_X4(pa[kk], pbase + kk * 32);

        // ---- O = O*alpha + P @ V ----
        #pragma unroll
        for (int nb = 0; nb < 8; ++nb) {
            o[nb][0] *= a0; o[nb][1] *= a0; o[nb][2] *= a1; o[nb][3] *= a1;
        }
        #pragma unroll
        for (int nbp = 0; nbp < 4; ++nbp) {
            #pragma unroll
            for (int kk = 0; kk < 4; ++kk) {
                uint32_t b[4];
                LDSM_X4_T(b, vbase + kk * 2304 + nbp * 32);
                mma16(o[2 * nbp],     pa[kk], b[0], b[1]);
                mma16(o[2 * nbp + 1], pa[kk], b[2], b[3]);
            }
        }
    }

    // ---- epilogue ----
    const float inv0 = 1.0f / l0;
    const float inv1 = 1.0f / l1;
    #pragma unroll
    for (int nb = 0; nb < 8; ++nb) {
        float2 r0 = { o[nb][0] * inv0, o[nb][1] * inv0 };
        float2 r1 = { o[nb][2] * inv1, o[nb][3] * inv1 };
        *(float2*)(Ob + (g)     * DHEAD + 8 * nb + 2 * lt) = r0;
        *(float2*)(Ob + (g + 8) * DHEAD + 8 * nb + 2 * lt) = r1;
    }
}

extern "C" void kernel_launch(void* const* d_in, const int* in_sizes, int n_in,
                              void* d_out, int out_size)
{
    const float* Q = (const float*)d_in[0];
    const float* K = (const float*)d_in[1];
    const float* V = (const float*)d_in[2];
    float* O = (float*)d_out;

    dim3 grid(NSEQ / BM, BHCOUNT);   // 16 x 96 = 1536 CTAs
    attn_mma_f16<<<grid, NTHREADS>>>(Q, K, V, O);
}

// round 7
// speedup vs baseline: 9.2748x; 1.1597x over previous
#include <cuda_runtime.h>
#include <cuda_fp16.h>
#include <cstdint>

// B=8, H=12, N=1024, D=64, fp32 in/out.
// f16 prepass (K,V -> __device__ scratch) + cp.async double-buffered
// flash-attention with mma.sync.m16n8k16.f16 (fp32 accum) + ldmatrix.
#define BHCOUNT  96
#define NSEQ     1024
#define DHEAD    64
#define BM       64
#define BN       64
#define NTILES   (NSEQ / BN)
#define NTHREADS 128
#define SCALE    0.125f

// f16 scratch: 96*1024*64 halves per tensor = 12.58 MB each (static, no alloc)
#define NUV4 786432        // 96*1024*64*2B / 16B
__device__ uint4 KF16[NUV4];
__device__ uint4 VF16[NUV4];

// smem (bytes): rows of 64 halves (128B) padded to 144B (ldmatrix conflict-free)
#define ROWB   144
#define TILEB  (64 * ROWB)          // 9216
#define KB0    0
#define VB0    TILEB
#define KB1    (2 * TILEB)
#define VB1    (3 * TILEB)
#define SMEM_BYTES (4 * TILEB)      // 36864

__device__ __forceinline__ uint32_t smem_u32(const void* p) {
    uint32_t a;
    asm("{ .reg .u64 t; cvta.to.shared.u64 t, %1; cvt.u32.u64 %0, t; }" : "=r"(a) : "l"(p));
    return a;
}
__device__ __forceinline__ uint32_t pkh2(float x, float y) {
    __half2 h = __floats2half2_rn(x, y);
    return *(uint32_t*)&h;
}

#define CPA16(sa, gp) \
    asm volatile("cp.async.cg.shared.global [%0], [%1], 16;" \
                 :: "r"((uint32_t)(sa)), "l"((size_t)(gp)) : "memory")
#define CPA_COMMIT() asm volatile("cp.async.commit_group;" ::: "memory")
#define CPA_WAIT1()  asm volatile("cp.async.wait_group 1;" ::: "memory")
#define CPA_WAIT0()  asm volatile("cp.async.wait_group 0;" ::: "memory")

#define LDSM_X4(d, a) \
    asm volatile("ldmatrix.sync.aligned.m8n8.x4.shared.b16 {%0,%1,%2,%3}, [%4];" \
        : "=r"((d)[0]), "=r"((d)[1]), "=r"((d)[2]), "=r"((d)[3]) : "r"(a))
#define LDSM_X4_T(d, a) \
    asm volatile("ldmatrix.sync.aligned.m8n8.x4.trans.shared.b16 {%0,%1,%2,%3}, [%4];" \
        : "=r"((d)[0]), "=r"((d)[1]), "=r"((d)[2]), "=r"((d)[3]) : "r"(a))

__device__ __forceinline__ void mma16(float* d, const uint32_t* a, uint32_t b0, uint32_t b1) {
    asm volatile(
        "mma.sync.aligned.m16n8k16.row.col.f32.f16.f16.f32 "
        "{%0,%1,%2,%3}, {%4,%5,%6,%7}, {%8,%9}, {%0,%1,%2,%3};"
        : "+f"(d[0]), "+f"(d[1]), "+f"(d[2]), "+f"(d[3])
        : "r"(a[0]), "r"(a[1]), "r"(a[2]), "r"(a[3]), "r"(b0), "r"(b1));
}

// ---------------- prepass: K,V f32 -> f16 scratch ----------------
__global__ __launch_bounds__(256)
void cvt_f16(const float4* __restrict__ K, const float4* __restrict__ V)
{
    int i0 = blockIdx.x * 256 + threadIdx.x;
    for (int u = i0; u < NUV4; u += gridDim.x * 256) {
        float4 a = K[2 * u], b = K[2 * u + 1];
        uint4 ko = { pkh2(a.x, a.y), pkh2(a.z, a.w), pkh2(b.x, b.y), pkh2(b.z, b.w) };
        KF16[u] = ko;
        a = V[2 * u]; b = V[2 * u + 1];
        uint4 vo = { pkh2(a.x, a.y), pkh2(a.z, a.w), pkh2(b.x, b.y), pkh2(b.z, b.w) };
        VF16[u] = vo;
    }
}

// ---------------- main attention kernel ----------------
__global__ __launch_bounds__(NTHREADS, 4)
void attn_mma_f16(const float* __restrict__ Qg_, float* __restrict__ Og_)
{
    __shared__ __align__(16) char sm[SMEM_BYTES];
    const uint32_t smb = smem_u32(sm);
    const int tid  = threadIdx.x;
    const int wid  = tid >> 5;
    const int lane = tid & 31;
    const int g    = lane >> 2;
    const int lt   = lane & 3;

    const int q0 = blockIdx.x * BM;
    const int bh = blockIdx.y;
    const float*  Qb = Qg_ + ((size_t)bh * NSEQ + q0 + wid * 16) * DHEAD;
    const __half* Kh = ((const __half*)KF16) + (size_t)bh * NSEQ * DHEAD;
    const __half* Vh = ((const __half*)VF16) + (size_t)bh * NSEQ * DHEAD;
    float*        Ob = Og_ + ((size_t)bh * NSEQ + q0 + wid * 16) * DHEAD;

    // ---- Q fragments (scale folded): 16 regs, resident all tiles ----
    uint32_t qa[4][4];
    {
        const float* q0r = Qb + g * DHEAD;
        const float* q1r = Qb + (g + 8) * DHEAD;
        #pragma unroll
        for (int kk = 0; kk < 4; ++kk) {
            int c = 16 * kk + 2 * lt;
            float2 x0 = *(const float2*)(q0r + c);
            float2 x1 = *(const float2*)(q1r + c);
            float2 x2 = *(const float2*)(q0r + c + 8);
            float2 x3 = *(const float2*)(q1r + c + 8);
            qa[kk][0] = pkh2(x0.x * SCALE, x0.y * SCALE);
            qa[kk][1] = pkh2(x1.x * SCALE, x1.y * SCALE);
            qa[kk][2] = pkh2(x2.x * SCALE, x2.y * SCALE);
            qa[kk][3] = pkh2(x3.x * SCALE, x3.y * SCALE);
        }
    }

    // ---- per-lane ldmatrix relative offsets (bytes) ----
    const uint32_t krel = (uint32_t)((8 * (lane >> 4) + (lane & 7)) * ROWB + ((lane >> 3) & 1) * 16);
    const uint32_t vrel = (uint32_t)((lane & 15) * ROWB + (lane >> 4) * 16);

    // cp.async staging: u = 0..511 per tensor; row = u>>3, seg = u&7
    const int srow = tid >> 3;                 // rows handled: srow, srow+16, +32, +48
    const int sseg = (tid & 7) * 16;           // byte seg in row (x8 halves)
    const int goff = srow * DHEAD + (tid & 7) * 8;

    // prologue: stage tile 0 into buffer 0
    {
        const __half* ks = Kh;
        const __half* vs = Vh;
        #pragma unroll
        for (int i = 0; i < 4; ++i) {
            uint32_t sa = smb + (srow + 16 * i) * ROWB + sseg;
            CPA16(sa + KB0, __cvta_generic_to_global(ks + goff + 16 * i * DHEAD));
            CPA16(sa + VB0, __cvta_generic_to_global(vs + goff + 16 * i * DHEAD));
        }
        CPA_COMMIT();
    }

    float o[8][4];
    #pragma unroll
    for (int nb = 0; nb < 8; ++nb)
        { o[nb][0] = 0.f; o[nb][1] = 0.f; o[nb][2] = 0.f; o[nb][3] = 0.f; }
    float m0 = -1e30f, m1 = -1e30f, l0 = 0.f, l1 = 0.f;

    for (int t = 0; t < NTILES; ++t) {
        const uint32_t kb = smb + ((t & 1) ? KB1 : KB0);
        const uint32_t vb = smb + ((t & 1) ? VB1 : VB0);

        // prefetch tile t+1 into the other buffer
        if (t + 1 < NTILES) {
            const __half* ks = Kh + (size_t)(t + 1) * BN * DHEAD;
            const __half* vs = Vh + (size_t)(t + 1) * BN * DHEAD;
            const uint32_t kn = smb + ((t & 1) ? KB0 : KB1);
            const uint32_t vn = smb + ((t & 1) ? VB0 : VB1);
            #pragma unroll
            for (int i = 0; i < 4; ++i) {
                uint32_t ra = (srow + 16 * i) * ROWB + sseg;
                CPA16(kn + ra, __cvta_generic_to_global(ks + goff + 16 * i * DHEAD));
                CPA16(vn + ra, __cvta_generic_to_global(vs + goff + 16 * i * DHEAD));
            }
            CPA_COMMIT();
            CPA_WAIT1();     // tile t's group complete (t+1 still in flight)
        } else {
            CPA_WAIT0();
        }
        __syncthreads();

        // ---- S = Q @ K^T ----
        float s[8][4];
        #pragma unroll
        for (int nb = 0; nb < 8; ++nb)
            { s[nb][0] = 0.f; s[nb][1] = 0.f; s[nb][2] = 0.f; s[nb][3] = 0.f; }
        #pragma unroll
        for (int nbp = 0; nbp < 4; ++nbp) {
            #pragma unroll
            for (int kk = 0; kk < 4; ++kk) {
                uint32_t b[4];
                LDSM_X4(b, kb + krel + nbp * (16 * ROWB) + kk * 32);
                mma16(s[2 * nbp],     qa[kk], b[0], b[1]);
                mma16(s[2 * nbp + 1], qa[kk], b[2], b[3]);
            }
        }

        // ---- online softmax (rows g, g+8) ----
        float mx0 = m0, mx1 = m1;
        #pragma unroll
        for (int nb = 0; nb < 8; ++nb) {
            mx0 = fmaxf(mx0, fmaxf(s[nb][0], s[nb][1]));
            mx1 = fmaxf(mx1, fmaxf(s[nb][2], s[nb][3]));
        }
        mx0 = fmaxf(mx0, __shfl_xor_sync(0xffffffffu, mx0, 1));
        mx0 = fmaxf(mx0, __shfl_xor_sync(0xffffffffu, mx0, 2));
        mx1 = fmaxf(mx1, __shfl_xor_sync(0xffffffffu, mx1, 1));
        mx1 = fmaxf(mx1, __shfl_xor_sync(0xffffffffu, mx1, 2));

        const float a0 = __expf(m0 - mx0);
        const float a1 = __expf(m1 - mx1);
        float rs0 = 0.f, rs1 = 0.f;
        #pragma unroll
        for (int nb = 0; nb < 8; ++nb) {
            s[nb][0] = __expf(s[nb][0] - mx0);
            s[nb][1] = __expf(s[nb][1] - mx0);
            s[nb][2] = __expf(s[nb][2] - mx1);
            s[nb][3] = __expf(s[nb][3] - mx1);
            rs0 += s[nb][0] + s[nb][1];
            rs1 += s[nb][2] + s[nb][3];
        }
        rs0 += __shfl_xor_sync(0xffffffffu, rs0, 1);
        rs0 += __shfl_xor_sync(0xffffffffu, rs0, 2);
        rs1 += __shfl_xor_sync(0xffffffffu, rs1, 1);
        rs1 += __shfl_xor_sync(0xffffffffu, rs1, 2);
        m0 = mx0; m1 = mx1;
        l0 = l0 * a0 + rs0;
        l1 = l1 * a1 + rs1;

        // ---- P A-fragments DIRECTLY from S C-fragments (no smem round-trip):
        //      a = { P[g][16kk+2lt..+1], P[g+8][same], P[g][+8], P[g+8][+8] }
        //        = { s[2kk][0..1], s[2kk][2..3], s[2kk+1][0..1], s[2kk+1][2..3] } ----
        uint32_t pa[4][4];
        #pragma unroll
        for (int kk = 0; kk < 4; ++kk) {
            pa[kk][0] = pkh2(s[2 * kk][0],     s[2 * kk][1]);
            pa[kk][1] = pkh2(s[2 * kk][2],     s[2 * kk][3]);
            pa[kk][2] = pkh2(s[2 * kk + 1][0], s[2 * kk + 1][1]);
            pa[kk][3] = pkh2(s[2 * kk + 1][2], s[2 * kk + 1][3]);
        }

        // ---- O = O*alpha + P @ V ----
        #pragma unroll
        for (int nb = 0; nb < 8; ++nb) {
            o[nb][0] *= a0; o[nb][1] *= a0; o[nb][2] *= a1; o[nb][3] *= a1;
        }
        #pragma unroll
        for (int nbp = 0; nbp < 4; ++nbp) {
            #pragma unroll
            for (int kk = 0; kk < 4; ++kk) {
                uint32_t b[4];
                LDSM_X4_T(b, vb + vrel + kk * (16 * ROWB) + nbp * 32);
                mma16(o[2 * nbp],     pa[kk], b[0], b[1]);
                mma16(o[2 * nbp + 1], pa[kk], b[2], b[3]);
            }
        }
        __syncthreads();   // all warps done reading this buffer before next prefetch lands
    }

    // ---- epilogue ----
    const float inv0 = 1.0f / l0;
    const float inv1 = 1.0f / l1;
    #pragma unroll
    for (int nb = 0; nb < 8; ++nb) {
        float2 r0 = { o[nb][0] * inv0, o[nb][1] * inv0 };
        float2 r1 = { o[nb][2] * inv1, o[nb][3] * inv1 };
        *(float2*)(Ob + (g)     * DHEAD + 8 * nb + 2 * lt) = r0;
        *(float2*)(Ob + (g + 8) * DHEAD + 8 * nb + 2 * lt) = r1;
    }
}

extern "C" void kernel_launch(void* const* d_in, const int* in_sizes, int n_in,
                              void* d_out, int out_size)
{
    const float* Q = (const float*)d_in[0];
    const float* K = (const float*)d_in[1];
    const float* V = (const float*)d_in[2];
    float* O = (float*)d_out;

    cvt_f16<<<768, 256>>>((const float4*)K, (const float4*)V);
    dim3 grid(NSEQ / BM, BHCOUNT);   // 16 x 96 = 1536 CTAs
    attn_mma_f16<<<grid, NTHREADS>>>(Q, O);
}